// round 15
// baseline (speedup 1.0000x reference)
#include <cuda_runtime.h>
#include <cuda_fp16.h>
#include <cstdint>

#define TOK 4096   // B*S tokens
#define HD  1024
#define NE  8
#define FF  4096
#define TOPK 2

// ---------------- scratch (device globals) ----------------
__device__ int   g_counts[NE];
__device__ int   g_tok[NE][TOK];
__device__ float g_wrow[NE][TOK];                                // per-slot combine weight
// fp16 operand copies (natural layouts)
__device__ __align__(16) __half g_xh[(size_t)TOK * HD];          // [t][k]
__device__ __align__(16) __half g_w1h[(size_t)NE * HD * FF];     // [e][k][n]
__device__ __align__(16) __half g_w3h[(size_t)NE * HD * FF];
__device__ __align__(16) __half g_w2h[(size_t)NE * FF * HD];     // [e][k][n]
__device__ __align__(16) __half g_hh[(size_t)TOK * TOPK * FF];   // SwiGLU out, fp16

// ---------------- helpers ----------------
__device__ __forceinline__ uint32_t smem_u32(const void* p) {
    uint32_t a;
    asm("{ .reg .u64 t; cvta.to.shared.u64 t, %1; cvt.u32.u64 %0, t; }" : "=r"(a) : "l"(p));
    return a;
}
__device__ __forceinline__ void mma16(float* d, const uint32_t* a, const uint32_t* b) {
    asm volatile("mma.sync.aligned.m16n8k16.row.col.f32.f16.f16.f32 "
        "{%0,%1,%2,%3}, {%4,%5,%6,%7}, {%8,%9}, {%0,%1,%2,%3};"
        : "+f"(d[0]), "+f"(d[1]), "+f"(d[2]), "+f"(d[3])
        : "r"(a[0]), "r"(a[1]), "r"(a[2]), "r"(a[3]), "r"(b[0]), "r"(b[1]));
}
__device__ __forceinline__ void ldmx4(uint32_t* r, uint32_t addr) {
    asm volatile("ldmatrix.sync.aligned.m8n8.x4.shared.b16 {%0,%1,%2,%3}, [%4];"
        : "=r"(r[0]), "=r"(r[1]), "=r"(r[2]), "=r"(r[3]) : "r"(addr));
}
__device__ __forceinline__ void ldmx4t(uint32_t* r, uint32_t addr) {
    asm volatile("ldmatrix.sync.aligned.m8n8.x4.trans.shared.b16 {%0,%1,%2,%3}, [%4];"
        : "=r"(r[0]), "=r"(r[1]), "=r"(r[2]), "=r"(r[3]) : "r"(addr));
}
#define CP16(dst32, src) \
    asm volatile("cp.async.cg.shared.global [%0], [%1], 16;" :: "r"(dst32), "l"(src) : "memory")
#define CP_COMMIT() asm volatile("cp.async.commit_group;" ::: "memory")
#define CP_WAIT0()  asm volatile("cp.async.wait_group 0;" ::: "memory")
#define CP_WAIT1()  asm volatile("cp.async.wait_group 1;" ::: "memory")
#define CP_WAIT2()  asm volatile("cp.async.wait_group 2;" ::: "memory")
#define REDADD(ptr, val) \
    asm volatile("red.global.add.f32 [%0], %1;" :: "l"(ptr), "f"(val) : "memory")
__device__ __forceinline__ uint32_t h2u(__half2 h) { return *reinterpret_cast<uint32_t*>(&h); }
__device__ __forceinline__ float silu_mul(float g, float u) {
    return __fdividef(g, 1.f + __expf(-g)) * u;
}

// ---------------- kernel 0: zero counters ----------------
__global__ void zero_counts_kernel() {
    if (threadIdx.x < NE) g_counts[threadIdx.x] = 0;
}

// ---------------- routing + x fp16 convert + out zeroing ----------------
__global__ void routing_kernel(const float* __restrict__ x,
                               const float* __restrict__ Wg,
                               const float* __restrict__ bg,
                               float* __restrict__ out) {
    const int t = blockIdx.x, tid = threadIdx.x, wid = tid >> 5, lid = tid & 31;
    __shared__ float s_logit[NE];
    const float* xt = x + (size_t)t * HD;

    {
        float4 v = ((const float4*)xt)[tid];
        uint2 o;
        o.x = h2u(__floats2half2_rn(v.x, v.y));
        o.y = h2u(__floats2half2_rn(v.z, v.w));
        ((uint2*)(g_xh + (size_t)t * HD))[tid] = o;
        ((float4*)(out + (size_t)t * HD))[tid] = make_float4(0.f, 0.f, 0.f, 0.f);
    }

    float acc = 0.f;
    for (int h = lid; h < HD; h += 32) acc += xt[h] * Wg[h * NE + wid];
    #pragma unroll
    for (int o = 16; o > 0; o >>= 1) acc += __shfl_down_sync(0xFFFFFFFFu, acc, o);
    if (lid == 0) s_logit[wid] = acc + bg[wid];
    __syncthreads();
    if (tid == 0) {
        float l[NE];
        #pragma unroll
        for (int e = 0; e < NE; e++) l[e] = s_logit[e];
        int i0 = 0;
        #pragma unroll
        for (int e = 1; e < NE; e++) if (l[e] > l[i0]) i0 = e;
        int i1 = (i0 == 0) ? 1 : 0;
        #pragma unroll
        for (int e = 0; e < NE; e++) if (e != i0 && l[e] > l[i1]) i1 = e;
        float w1 = __expf(l[i1] - l[i0]);
        float inv = __fdividef(1.f, 1.f + w1);
        int s0 = atomicAdd(&g_counts[i0], 1);
        int s1 = atomicAdd(&g_counts[i1], 1);
        g_tok[i0][s0] = t;  g_wrow[i0][s0] = inv;
        g_tok[i1][s1] = t;  g_wrow[i1][s1] = w1 * inv;
    }
}

// ---------------- prep: weight fp16 converts ----------------
__global__ void cvt_w13_kernel(const float4* __restrict__ W1, const float4* __restrict__ W3) {
    const int n4 = NE * HD * FF / 4;
    const int stride = gridDim.x * blockDim.x;
    for (int i = blockIdx.x * blockDim.x + threadIdx.x; i < n4; i += stride) {
        float4 a = W1[i], b = W3[i];
        uint2 oa, ob;
        oa.x = h2u(__floats2half2_rn(a.x, a.y)); oa.y = h2u(__floats2half2_rn(a.z, a.w));
        ob.x = h2u(__floats2half2_rn(b.x, b.y)); ob.y = h2u(__floats2half2_rn(b.z, b.w));
        ((uint2*)g_w1h)[i] = oa;
        ((uint2*)g_w3h)[i] = ob;
    }
}
__global__ void cvt_w2_kernel(const float4* __restrict__ W2) {
    const int n4 = NE * FF * HD / 4;
    const int stride = gridDim.x * blockDim.x;
    for (int i = blockIdx.x * blockDim.x + threadIdx.x; i < n4; i += stride) {
        float4 v = W2[i];
        uint2 o;
        o.x = h2u(__floats2half2_rn(v.x, v.y));
        o.y = h2u(__floats2half2_rn(v.z, v.w));
        ((uint2*)g_w2h)[i] = o;
    }
}

// ======================= GEMM1 (fp16, BK=64) =======================
#define G1_A_OFF  512
#define G1_A_STG  18432
#define G1_B1_OFF (512 + 3 * 18432)           /* 55808 */
#define G1_B_STG  9216
#define G1_B3_OFF (55808 + 3 * 9216)          /* 83456 */
#define G1_SMEM   (83456 + 3 * 9216)          /* 111104 */

__device__ __forceinline__ void g1_load_stage(uint32_t sb, int s, int c,
                                              const int* toks,
                                              const __half* __restrict__ W1h,
                                              const __half* __restrict__ W3h,
                                              int n0, int tid) {
    const int k0 = c * 64;
    const uint32_t aB = sb + G1_A_OFF + s * G1_A_STG;
    #pragma unroll
    for (int q = 0; q < 4; q++) {
        int id = q * 256 + tid, row = id >> 3, gq = id & 7;
        CP16(aB + row * 144 + gq * 16, g_xh + (size_t)toks[row] * HD + k0 + gq * 8);
    }
    const uint32_t b1B = sb + G1_B1_OFF + s * G1_B_STG;
    const uint32_t b3B = sb + G1_B3_OFF + s * G1_B_STG;
    #pragma unroll
    for (int q = 0; q < 2; q++) {
        int id = q * 256 + tid, row = id >> 3, gq = id & 7;
        size_t off = (size_t)(k0 + row) * FF + n0 + gq * 8;
        uint32_t so = row * 144 + gq * 16;
        CP16(b1B + so, W1h + off);
        CP16(b3B + so, W3h + off);
    }
    CP_COMMIT();
}

__global__ __launch_bounds__(256, 2) void gemm1_mma(int e) {
    int n = 0, base = 0;
    #pragma unroll
    for (int i = 0; i < NE; i++) {
        int ci = g_counts[i];
        if (i < e) base += ci;
        if (i == e) n = ci;
    }
    const int m0 = blockIdx.y * 128;
    if (m0 >= n) return;
    const int n0 = blockIdx.x * 64;

    extern __shared__ char dynsmem[];
    const uint32_t sb = smem_u32(dynsmem);
    int* toks = (int*)dynsmem;

    const int tid = threadIdx.x, wid = tid >> 5, lane = tid & 31;
    const int g = lane >> 2, tig = lane & 3;
    const int wm = wid >> 1, wn = wid & 1;

    if (tid < 128) { int r = m0 + tid; toks[tid] = g_tok[e][r < n ? r : n - 1]; }
    __syncthreads();

    const __half* __restrict__ W1h = g_w1h + (size_t)e * HD * FF;
    const __half* __restrict__ W3h = g_w3h + (size_t)e * HD * FF;

    float cg[2][4][4] = {};
    float cu[2][4][4] = {};

    const uint32_t aAddr  = sb + G1_A_OFF + (wm * 32 + (lane & 15)) * 144 + (lane >> 4) * 16;
    const uint32_t bOff   = (lane & 15) * 144 + (lane >> 4) * 16 + wn * 64;
    const uint32_t b1Addr = sb + G1_B1_OFF + bOff;
    const uint32_t b3Addr = sb + G1_B3_OFF + bOff;

    uint32_t Af[2][2][4], B1f[2][2][4], B3f[2][2][4];

    g1_load_stage(sb, 0, 0, toks, W1h, W3h, n0, tid);
    g1_load_stage(sb, 1, 1, toks, W1h, W3h, n0, tid);
    g1_load_stage(sb, 2, 2, toks, W1h, W3h, n0, tid);
    CP_WAIT2();
    __syncthreads();
    ldmx4(Af[0][0], aAddr);
    ldmx4(Af[0][1], aAddr + 16 * 144);
    ldmx4t(B1f[0][0], b1Addr);
    ldmx4t(B1f[0][1], b1Addr + 32);
    ldmx4t(B3f[0][0], b3Addr);
    ldmx4t(B3f[0][1], b3Addr + 32);

    const int NC = HD / 64;   // 16 chunks
    for (int c = 0; c < NC; c++) {
        const int s = c % 3;
        const uint32_t aS  = aAddr  + s * G1_A_STG;
        const uint32_t b1S = b1Addr + s * G1_B_STG;
        const uint32_t b3S = b3Addr + s * G1_B_STG;

        #pragma unroll
        for (int ks = 0; ks < 4; ks++) {
            const int cur = ks & 1;
            if (ks < 3) {
                const int nxt = cur ^ 1;
                const uint32_t ao = aS + (ks + 1) * 32;
                const uint32_t bo = (ks + 1) * 2304;
                ldmx4(Af[nxt][0], ao);
                ldmx4(Af[nxt][1], ao + 16 * 144);
                ldmx4t(B1f[nxt][0], b1S + bo);
                ldmx4t(B1f[nxt][1], b1S + bo + 32);
                ldmx4t(B3f[nxt][0], b3S + bo);
                ldmx4t(B3f[nxt][1], b3S + bo + 32);
            }
            #pragma unroll
            for (int nt = 0; nt < 4; nt++) {
                const uint32_t* b1 = &B1f[cur][nt >> 1][(nt & 1) * 2];
                const uint32_t* b3 = &B3f[cur][nt >> 1][(nt & 1) * 2];
                #pragma unroll
                for (int mt = 0; mt < 2; mt++) {
                    mma16(cg[mt][nt], Af[cur][mt], b1);
                    mma16(cu[mt][nt], Af[cur][mt], b3);
                }
            }
        }

        if (c + 1 < NC) {
            if (c + 2 < NC) { CP_WAIT1(); } else { CP_WAIT0(); }
            __syncthreads();
            const int s1 = (c + 1) % 3;
            const uint32_t aN  = aAddr  + s1 * G1_A_STG;
            const uint32_t b1N = b1Addr + s1 * G1_B_STG;
            const uint32_t b3N = b3Addr + s1 * G1_B_STG;
            ldmx4(Af[0][0], aN);
            ldmx4(Af[0][1], aN + 16 * 144);
            ldmx4t(B1f[0][0], b1N);
            ldmx4t(B1f[0][1], b1N + 32);
            ldmx4t(B3f[0][0], b3N);
            ldmx4t(B3f[0][1], b3N + 32);
            if (c + 3 < NC)
                g1_load_stage(sb, s, c + 3, toks, W1h, W3h, n0, tid);
        }
    }

    // epilogue: h = silu(g) * u -> fp16 g_hh
    #pragma unroll
    for (int mt = 0; mt < 2; mt++) {
        #pragma unroll
        for (int half_ = 0; half_ < 2; half_++) {
            const int r = m0 + wm * 32 + mt * 16 + g + half_ * 8;
            if (r >= n) continue;
            __half2* hp = (__half2*)(g_hh + (size_t)(base + r) * FF + n0 + wn * 32 + 2 * tig);
            #pragma unroll
            for (int nt = 0; nt < 4; nt++) {
                float o0 = silu_mul(cg[mt][nt][half_ * 2 + 0], cu[mt][nt][half_ * 2 + 0]);
                float o1 = silu_mul(cg[mt][nt][half_ * 2 + 1], cu[mt][nt][half_ * 2 + 1]);
                hp[nt * 4] = __floats2half2_rn(o0, o1);
            }
        }
    }
}

// ======================= GEMM2 (fp16, BK=64) — fused weighted scatter-add =======================
#define G2_A_STG 18432
#define G2_B_OFF (3 * 18432)                  /* 55296 */
#define G2_B_STG 17408
#define G2_SMEM  (55296 + 3 * 17408)          /* 107520 */

__device__ __forceinline__ void g2_load_stage(uint32_t sb, int s, int c,
                                              const __half* __restrict__ W2h,
                                              int base, int m0, int n, int n0, int tid) {
    const int k0 = c * 64;
    const uint32_t aB = sb + s * G2_A_STG;
    #pragma unroll
    for (int q = 0; q < 4; q++) {
        int id = q * 256 + tid, row = id >> 3, gq = id & 7;
        int rg = m0 + row; if (rg >= n) rg = n - 1;
        CP16(aB + row * 144 + gq * 16, g_hh + (size_t)(base + rg) * FF + k0 + gq * 8);
    }
    const uint32_t bB = sb + G2_B_OFF + s * G2_B_STG;
    #pragma unroll
    for (int q = 0; q < 4; q++) {
        int id = q * 256 + tid, row = id >> 4, gq = id & 15;
        CP16(bB + row * 272 + gq * 16, W2h + (size_t)(k0 + row) * HD + n0 + gq * 8);
    }
    CP_COMMIT();
}

__global__ __launch_bounds__(256, 2) void gemm2_mma(float* __restrict__ out, int e) {
    int n = 0, base = 0;
    #pragma unroll
    for (int i = 0; i < NE; i++) {
        int ci = g_counts[i];
        if (i < e) base += ci;
        if (i == e) n = ci;
    }
    const int m0 = blockIdx.y * 128;
    if (m0 >= n) return;
    const int n0 = blockIdx.x * 128;

    extern __shared__ char dynsmem[];
    const uint32_t sb = smem_u32(dynsmem);

    const int tid = threadIdx.x, wid = tid >> 5, lane = tid & 31;
    const int g = lane >> 2, tig = lane & 3;
    const int wm = wid >> 1, wn = wid & 1;

    const __half* __restrict__ W2h = g_w2h + (size_t)e * FF * HD;

    float cacc[2][8][4] = {};

    const uint32_t aAddr = sb + (wm * 32 + (lane & 15)) * 144 + (lane >> 4) * 16;
    const uint32_t bAddr = sb + G2_B_OFF + (lane & 15) * 272 + (lane >> 4) * 16 + wn * 128;

    uint32_t Af[2][2][4], Bf[2][4][4];

    g2_load_stage(sb, 0, 0, W2h, base, m0, n, n0, tid);
    g2_load_stage(sb, 1, 1, W2h, base, m0, n, n0, tid);
    g2_load_stage(sb, 2, 2, W2h, base, m0, n, n0, tid);
    CP_WAIT2();
    __syncthreads();
    ldmx4(Af[0][0], aAddr);
    ldmx4(Af[0][1], aAddr + 16 * 144);
    #pragma unroll
    for (int p = 0; p < 4; p++)
        ldmx4t(Bf[0][p], bAddr + p * 32);

    const int NC = FF / 64;   // 64 chunks
    for (int c = 0; c < NC; c++) {
        const int s = c % 3;
        const uint32_t aS = aAddr + s * G2_A_STG;
        const uint32_t bS = bAddr + s * G2_B_STG;

        #pragma unroll
        for (int ks = 0; ks < 4; ks++) {
            const int cur = ks & 1;
            if (ks < 3) {
                const int nxt = cur ^ 1;
                const uint32_t ao = aS + (ks + 1) * 32;
                const uint32_t bo = bS + (ks + 1) * 4352;
                ldmx4(Af[nxt][0], ao);
                ldmx4(Af[nxt][1], ao + 16 * 144);
                #pragma unroll
                for (int p = 0; p < 4; p++)
                    ldmx4t(Bf[nxt][p], bo + p * 32);
            }
            #pragma unroll
            for (int nt = 0; nt < 8; nt++) {
                const uint32_t* b = &Bf[cur][nt >> 1][(nt & 1) * 2];
                #pragma unroll
                for (int mt = 0; mt < 2; mt++)
                    mma16(cacc[mt][nt], Af[cur][mt], b);
            }
        }

        if (c + 1 < NC) {
            if (c + 2 < NC) { CP_WAIT1(); } else { CP_WAIT0(); }
            __syncthreads();
            const int s1 = (c + 1) % 3;
            const uint32_t aN = aAddr + s1 * G2_A_STG;
            const uint32_t bN = bAddr + s1 * G2_B_STG;
            ldmx4(Af[0][0], aN);
            ldmx4(Af[0][1], aN + 16 * 144);
            #pragma unroll
            for (int p = 0; p < 4; p++)
                ldmx4t(Bf[0][p], bN + p * 32);
            if (c + 3 < NC)
                g2_load_stage(sb, s, c + 3, W2h, base, m0, n, n0, tid);
        }
    }

    // epilogue: weighted scatter-add into out
    #pragma unroll
    for (int mt = 0; mt < 2; mt++) {
        #pragma unroll
        for (int half_ = 0; half_ < 2; half_++) {
            const int r = m0 + wm * 32 + mt * 16 + g + half_ * 8;
            if (r >= n) continue;
            const int tk = g_tok[e][r];
            const float w = g_wrow[e][r];
            float* op = out + (size_t)tk * HD + n0 + wn * 64 + 2 * tig;
            #pragma unroll
            for (int nt = 0; nt < 8; nt++) {
                REDADD(op + nt * 8,     w * cacc[mt][nt][half_ * 2 + 0]);
                REDADD(op + nt * 8 + 1, w * cacc[mt][nt][half_ * 2 + 1]);
            }
        }
    }
}

// ---------------- launcher: expert-pipelined fork/join (graph-capture safe) ----------------
extern "C" void kernel_launch(void* const* d_in, const int* in_sizes, int n_in,
                              void* d_out, int out_size) {
    const float* x  = (const float*)d_in[0];
    const float* Wg = (const float*)d_in[1];
    const float* bg = (const float*)d_in[2];
    const float* W1 = (const float*)d_in[3];
    const float* W3 = (const float*)d_in[4];
    const float* W2 = (const float*)d_in[5];
    float* out = (float*)d_out;

    cudaFuncSetAttribute(gemm1_mma, cudaFuncAttributeMaxDynamicSharedMemorySize, G1_SMEM);
    cudaFuncSetAttribute(gemm2_mma, cudaFuncAttributeMaxDynamicSharedMemorySize, G2_SMEM);

    cudaStream_t sW;
    cudaStreamCreateWithFlags(&sW, cudaStreamNonBlocking);
    cudaEvent_t evStart, evW13, ev1[NE], evDone;
    cudaEventCreateWithFlags(&evStart, cudaEventDisableTiming);
    cudaEventCreateWithFlags(&evW13,  cudaEventDisableTiming);
    for (int e = 0; e < NE; e++) cudaEventCreateWithFlags(&ev1[e], cudaEventDisableTiming);
    cudaEventCreateWithFlags(&evDone, cudaEventDisableTiming);

    // fork side stream for weight converts
    zero_counts_kernel<<<1, 32>>>();
    cudaEventRecord(evStart, 0);
    cudaStreamWaitEvent(sW, evStart, 0);
    cvt_w13_kernel<<<4096, 256, 0, sW>>>((const float4*)W1, (const float4*)W3);
    cudaEventRecord(evW13, sW);
    cvt_w2_kernel<<<4096, 256, 0, sW>>>((const float4*)W2);   // stream-ordered before gemm2 chain

    routing_kernel<<<TOK, 256>>>(x, Wg, bg, out);
    cudaStreamWaitEvent(0, evW13, 0);                         // main needs W1/W3 before gemm1

    // expert-pipelined GEMMs: gemm2(e) on side stream waits only on gemm1(e)
    for (int e = 0; e < NE; e++) {
        gemm1_mma<<<dim3(FF / 64, TOK / 128, 1), 256, G1_SMEM>>>(e);
        cudaEventRecord(ev1[e], 0);
        cudaStreamWaitEvent(sW, ev1[e], 0);
        gemm2_mma<<<dim3(HD / 128, TOK / 128, 1), 256, G2_SMEM, sW>>>(out, e);
    }
    cudaEventRecord(evDone, sW);
    cudaStreamWaitEvent(0, evDone, 0);                        // join side stream back
}

// round 16
// speedup vs baseline: 1.2848x; 1.2848x over previous
#include <cuda_runtime.h>
#include <cuda_fp16.h>
#include <cstdint>

#define TOK 4096   // B*S tokens
#define HD  1024
#define NE  8
#define FF  4096
#define TOPK 2

// ---------------- scratch (device globals) ----------------
__device__ int   g_counts[NE];
__device__ int   g_tok[NE][TOK];
__device__ float g_wrow[NE][TOK];                                // per-slot combine weight
// fp16 operand copies (natural layouts)
__device__ __align__(16) __half g_xh[(size_t)TOK * HD];          // [t][k]
__device__ __align__(16) __half g_w1h[(size_t)NE * HD * FF];     // [e][k][n]
__device__ __align__(16) __half g_w3h[(size_t)NE * HD * FF];
__device__ __align__(16) __half g_w2h[(size_t)NE * FF * HD];     // [e][k][n]
__device__ __align__(16) __half g_hh[(size_t)TOK * TOPK * FF];   // SwiGLU out, fp16

// ---------------- helpers ----------------
__device__ __forceinline__ uint32_t smem_u32(const void* p) {
    uint32_t a;
    asm("{ .reg .u64 t; cvta.to.shared.u64 t, %1; cvt.u32.u64 %0, t; }" : "=r"(a) : "l"(p));
    return a;
}
__device__ __forceinline__ void mma16(float* d, const uint32_t* a, const uint32_t* b) {
    asm volatile("mma.sync.aligned.m16n8k16.row.col.f32.f16.f16.f32 "
        "{%0,%1,%2,%3}, {%4,%5,%6,%7}, {%8,%9}, {%0,%1,%2,%3};"
        : "+f"(d[0]), "+f"(d[1]), "+f"(d[2]), "+f"(d[3])
        : "r"(a[0]), "r"(a[1]), "r"(a[2]), "r"(a[3]), "r"(b[0]), "r"(b[1]));
}
__device__ __forceinline__ void ldmx4(uint32_t* r, uint32_t addr) {
    asm volatile("ldmatrix.sync.aligned.m8n8.x4.shared.b16 {%0,%1,%2,%3}, [%4];"
        : "=r"(r[0]), "=r"(r[1]), "=r"(r[2]), "=r"(r[3]) : "r"(addr));
}
__device__ __forceinline__ void ldmx4t(uint32_t* r, uint32_t addr) {
    asm volatile("ldmatrix.sync.aligned.m8n8.x4.trans.shared.b16 {%0,%1,%2,%3}, [%4];"
        : "=r"(r[0]), "=r"(r[1]), "=r"(r[2]), "=r"(r[3]) : "r"(addr));
}
#define CP16(dst32, src) \
    asm volatile("cp.async.cg.shared.global [%0], [%1], 16;" :: "r"(dst32), "l"(src) : "memory")
#define CP_COMMIT() asm volatile("cp.async.commit_group;" ::: "memory")
#define CP_WAIT0()  asm volatile("cp.async.wait_group 0;" ::: "memory")
#define CP_WAIT1()  asm volatile("cp.async.wait_group 1;" ::: "memory")
#define CP_WAIT2()  asm volatile("cp.async.wait_group 2;" ::: "memory")
#define REDADD(ptr, val) \
    asm volatile("red.global.add.f32 [%0], %1;" :: "l"(ptr), "f"(val) : "memory")
__device__ __forceinline__ uint32_t h2u(__half2 h) { return *reinterpret_cast<uint32_t*>(&h); }
__device__ __forceinline__ float silu_mul(float g, float u) {
    return __fdividef(g, 1.f + __expf(-g)) * u;
}

// ---------------- kernel 0: zero counters ----------------
__global__ void zero_counts_kernel() {
    if (threadIdx.x < NE) g_counts[threadIdx.x] = 0;
}

// ---------------- routing + x fp16 convert + out zeroing ----------------
__global__ void routing_kernel(const float* __restrict__ x,
                               const float* __restrict__ Wg,
                               const float* __restrict__ bg,
                               float* __restrict__ out) {
    const int t = blockIdx.x, tid = threadIdx.x, wid = tid >> 5, lid = tid & 31;
    __shared__ float s_logit[NE];
    const float* xt = x + (size_t)t * HD;

    {
        float4 v = ((const float4*)xt)[tid];
        uint2 o;
        o.x = h2u(__floats2half2_rn(v.x, v.y));
        o.y = h2u(__floats2half2_rn(v.z, v.w));
        ((uint2*)(g_xh + (size_t)t * HD))[tid] = o;
        ((float4*)(out + (size_t)t * HD))[tid] = make_float4(0.f, 0.f, 0.f, 0.f);
    }

    float acc = 0.f;
    for (int h = lid; h < HD; h += 32) acc += xt[h] * Wg[h * NE + wid];
    #pragma unroll
    for (int o = 16; o > 0; o >>= 1) acc += __shfl_down_sync(0xFFFFFFFFu, acc, o);
    if (lid == 0) s_logit[wid] = acc + bg[wid];
    __syncthreads();
    if (tid == 0) {
        float l[NE];
        #pragma unroll
        for (int e = 0; e < NE; e++) l[e] = s_logit[e];
        int i0 = 0;
        #pragma unroll
        for (int e = 1; e < NE; e++) if (l[e] > l[i0]) i0 = e;
        int i1 = (i0 == 0) ? 1 : 0;
        #pragma unroll
        for (int e = 0; e < NE; e++) if (e != i0 && l[e] > l[i1]) i1 = e;
        float w1 = __expf(l[i1] - l[i0]);
        float inv = __fdividef(1.f, 1.f + w1);
        int s0 = atomicAdd(&g_counts[i0], 1);
        int s1 = atomicAdd(&g_counts[i1], 1);
        g_tok[i0][s0] = t;  g_wrow[i0][s0] = inv;
        g_tok[i1][s1] = t;  g_wrow[i1][s1] = w1 * inv;
    }
}

// ---------------- prep: weight fp16 converts ----------------
__global__ void cvt_w13_kernel(const float4* __restrict__ W1, const float4* __restrict__ W3) {
    const int n4 = NE * HD * FF / 4;
    const int stride = gridDim.x * blockDim.x * 2;
    for (int i = (blockIdx.x * blockDim.x + threadIdx.x) * 2; i < n4; i += stride) {
        float4 a0 = W1[i], a1 = W1[i + 1], b0 = W3[i], b1 = W3[i + 1];
        uint2 oa0, oa1, ob0, ob1;
        oa0.x = h2u(__floats2half2_rn(a0.x, a0.y)); oa0.y = h2u(__floats2half2_rn(a0.z, a0.w));
        oa1.x = h2u(__floats2half2_rn(a1.x, a1.y)); oa1.y = h2u(__floats2half2_rn(a1.z, a1.w));
        ob0.x = h2u(__floats2half2_rn(b0.x, b0.y)); ob0.y = h2u(__floats2half2_rn(b0.z, b0.w));
        ob1.x = h2u(__floats2half2_rn(b1.x, b1.y)); ob1.y = h2u(__floats2half2_rn(b1.z, b1.w));
        ((uint2*)g_w1h)[i] = oa0;  ((uint2*)g_w1h)[i + 1] = oa1;
        ((uint2*)g_w3h)[i] = ob0;  ((uint2*)g_w3h)[i + 1] = ob1;
    }
}
__global__ void cvt_w2_kernel(const float4* __restrict__ W2) {
    const int n4 = NE * FF * HD / 4;
    const int stride = gridDim.x * blockDim.x;
    for (int i = blockIdx.x * blockDim.x + threadIdx.x; i < n4; i += stride) {
        float4 v = W2[i];
        uint2 o;
        o.x = h2u(__floats2half2_rn(v.x, v.y));
        o.y = h2u(__floats2half2_rn(v.z, v.w));
        ((uint2*)g_w2h)[i] = o;
    }
}

// ======================= GEMM1 (fp16, BK=64) =======================
#define G1_A_OFF  512
#define G1_A_STG  18432
#define G1_B1_OFF (512 + 3 * 18432)           /* 55808 */
#define G1_B_STG  9216
#define G1_B3_OFF (55808 + 3 * 9216)          /* 83456 */
#define G1_SMEM   (83456 + 3 * 9216)          /* 111104 */

__device__ __forceinline__ void g1_load_stage(uint32_t sb, int s, int c,
                                              const int* toks,
                                              const __half* __restrict__ W1h,
                                              const __half* __restrict__ W3h,
                                              int n0, int tid) {
    const int k0 = c * 64;
    const uint32_t aB = sb + G1_A_OFF + s * G1_A_STG;
    #pragma unroll
    for (int q = 0; q < 4; q++) {
        int id = q * 256 + tid, row = id >> 3, gq = id & 7;
        CP16(aB + row * 144 + gq * 16, g_xh + (size_t)toks[row] * HD + k0 + gq * 8);
    }
    const uint32_t b1B = sb + G1_B1_OFF + s * G1_B_STG;
    const uint32_t b3B = sb + G1_B3_OFF + s * G1_B_STG;
    #pragma unroll
    for (int q = 0; q < 2; q++) {
        int id = q * 256 + tid, row = id >> 3, gq = id & 7;
        size_t off = (size_t)(k0 + row) * FF + n0 + gq * 8;
        uint32_t so = row * 144 + gq * 16;
        CP16(b1B + so, W1h + off);
        CP16(b3B + so, W3h + off);
    }
    CP_COMMIT();
}

__global__ __launch_bounds__(256, 2) void gemm1_mma(int e0) {
    const int e = e0 + blockIdx.z;
    int n = 0, base = 0;
    #pragma unroll
    for (int i = 0; i < NE; i++) {
        int ci = g_counts[i];
        if (i < e) base += ci;
        if (i == e) n = ci;
    }
    const int m0 = blockIdx.y * 128;
    if (m0 >= n) return;
    const int n0 = blockIdx.x * 64;

    extern __shared__ char dynsmem[];
    const uint32_t sb = smem_u32(dynsmem);
    int* toks = (int*)dynsmem;

    const int tid = threadIdx.x, wid = tid >> 5, lane = tid & 31;
    const int g = lane >> 2, tig = lane & 3;
    const int wm = wid >> 1, wn = wid & 1;

    if (tid < 128) { int r = m0 + tid; toks[tid] = g_tok[e][r < n ? r : n - 1]; }
    __syncthreads();

    const __half* __restrict__ W1h = g_w1h + (size_t)e * HD * FF;
    const __half* __restrict__ W3h = g_w3h + (size_t)e * HD * FF;

    float cg[2][4][4] = {};
    float cu[2][4][4] = {};

    const uint32_t aAddr  = sb + G1_A_OFF + (wm * 32 + (lane & 15)) * 144 + (lane >> 4) * 16;
    const uint32_t bOff   = (lane & 15) * 144 + (lane >> 4) * 16 + wn * 64;
    const uint32_t b1Addr = sb + G1_B1_OFF + bOff;
    const uint32_t b3Addr = sb + G1_B3_OFF + bOff;

    uint32_t Af[2][2][4], B1f[2][2][4], B3f[2][2][4];

    g1_load_stage(sb, 0, 0, toks, W1h, W3h, n0, tid);
    g1_load_stage(sb, 1, 1, toks, W1h, W3h, n0, tid);
    g1_load_stage(sb, 2, 2, toks, W1h, W3h, n0, tid);
    CP_WAIT2();
    __syncthreads();
    ldmx4(Af[0][0], aAddr);
    ldmx4(Af[0][1], aAddr + 16 * 144);
    ldmx4t(B1f[0][0], b1Addr);
    ldmx4t(B1f[0][1], b1Addr + 32);
    ldmx4t(B3f[0][0], b3Addr);
    ldmx4t(B3f[0][1], b3Addr + 32);

    const int NC = HD / 64;   // 16 chunks
    for (int c = 0; c < NC; c++) {
        const int s = c % 3;
        const uint32_t aS  = aAddr  + s * G1_A_STG;
        const uint32_t b1S = b1Addr + s * G1_B_STG;
        const uint32_t b3S = b3Addr + s * G1_B_STG;

        #pragma unroll
        for (int ks = 0; ks < 4; ks++) {
            const int cur = ks & 1;
            if (ks < 3) {
                const int nxt = cur ^ 1;
                const uint32_t ao = aS + (ks + 1) * 32;
                const uint32_t bo = (ks + 1) * 2304;
                ldmx4(Af[nxt][0], ao);
                ldmx4(Af[nxt][1], ao + 16 * 144);
                ldmx4t(B1f[nxt][0], b1S + bo);
                ldmx4t(B1f[nxt][1], b1S + bo + 32);
                ldmx4t(B3f[nxt][0], b3S + bo);
                ldmx4t(B3f[nxt][1], b3S + bo + 32);
            }
            #pragma unroll
            for (int nt = 0; nt < 4; nt++) {
                const uint32_t* b1 = &B1f[cur][nt >> 1][(nt & 1) * 2];
                const uint32_t* b3 = &B3f[cur][nt >> 1][(nt & 1) * 2];
                #pragma unroll
                for (int mt = 0; mt < 2; mt++) {
                    mma16(cg[mt][nt], Af[cur][mt], b1);
                    mma16(cu[mt][nt], Af[cur][mt], b3);
                }
            }
        }

        if (c + 1 < NC) {
            if (c + 2 < NC) { CP_WAIT1(); } else { CP_WAIT0(); }
            __syncthreads();
            const int s1 = (c + 1) % 3;
            const uint32_t aN  = aAddr  + s1 * G1_A_STG;
            const uint32_t b1N = b1Addr + s1 * G1_B_STG;
            const uint32_t b3N = b3Addr + s1 * G1_B_STG;
            ldmx4(Af[0][0], aN);
            ldmx4(Af[0][1], aN + 16 * 144);
            ldmx4t(B1f[0][0], b1N);
            ldmx4t(B1f[0][1], b1N + 32);
            ldmx4t(B3f[0][0], b3N);
            ldmx4t(B3f[0][1], b3N + 32);
            if (c + 3 < NC)
                g1_load_stage(sb, s, c + 3, toks, W1h, W3h, n0, tid);
        }
    }

    // epilogue: h = silu(g) * u -> fp16 g_hh
    #pragma unroll
    for (int mt = 0; mt < 2; mt++) {
        #pragma unroll
        for (int half_ = 0; half_ < 2; half_++) {
            const int r = m0 + wm * 32 + mt * 16 + g + half_ * 8;
            if (r >= n) continue;
            __half2* hp = (__half2*)(g_hh + (size_t)(base + r) * FF + n0 + wn * 32 + 2 * tig);
            #pragma unroll
            for (int nt = 0; nt < 4; nt++) {
                float o0 = silu_mul(cg[mt][nt][half_ * 2 + 0], cu[mt][nt][half_ * 2 + 0]);
                float o1 = silu_mul(cg[mt][nt][half_ * 2 + 1], cu[mt][nt][half_ * 2 + 1]);
                hp[nt * 4] = __floats2half2_rn(o0, o1);
            }
        }
    }
}

// ======================= GEMM2 (fp16, BK=64) — fused weighted scatter-add =======================
#define G2_A_STG 18432
#define G2_B_OFF (3 * 18432)                  /* 55296 */
#define G2_B_STG 17408
#define G2_SMEM  (55296 + 3 * 17408)          /* 107520 */

__device__ __forceinline__ void g2_load_stage(uint32_t sb, int s, int c,
                                              const __half* __restrict__ W2h,
                                              int base, int m0, int n, int n0, int tid) {
    const int k0 = c * 64;
    const uint32_t aB = sb + s * G2_A_STG;
    #pragma unroll
    for (int q = 0; q < 4; q++) {
        int id = q * 256 + tid, row = id >> 3, gq = id & 7;
        int rg = m0 + row; if (rg >= n) rg = n - 1;
        CP16(aB + row * 144 + gq * 16, g_hh + (size_t)(base + rg) * FF + k0 + gq * 8);
    }
    const uint32_t bB = sb + G2_B_OFF + s * G2_B_STG;
    #pragma unroll
    for (int q = 0; q < 4; q++) {
        int id = q * 256 + tid, row = id >> 4, gq = id & 15;
        CP16(bB + row * 272 + gq * 16, W2h + (size_t)(k0 + row) * HD + n0 + gq * 8);
    }
    CP_COMMIT();
}

__global__ __launch_bounds__(256, 2) void gemm2_mma(float* __restrict__ out, int e0) {
    const int e = e0 + blockIdx.z;
    int n = 0, base = 0;
    #pragma unroll
    for (int i = 0; i < NE; i++) {
        int ci = g_counts[i];
        if (i < e) base += ci;
        if (i == e) n = ci;
    }
    const int m0 = blockIdx.y * 128;
    if (m0 >= n) return;
    const int n0 = blockIdx.x * 128;

    extern __shared__ char dynsmem[];
    const uint32_t sb = smem_u32(dynsmem);

    const int tid = threadIdx.x, wid = tid >> 5, lane = tid & 31;
    const int g = lane >> 2, tig = lane & 3;
    const int wm = wid >> 1, wn = wid & 1;

    const __half* __restrict__ W2h = g_w2h + (size_t)e * FF * HD;

    float cacc[2][8][4] = {};

    const uint32_t aAddr = sb + (wm * 32 + (lane & 15)) * 144 + (lane >> 4) * 16;
    const uint32_t bAddr = sb + G2_B_OFF + (lane & 15) * 272 + (lane >> 4) * 16 + wn * 128;

    uint32_t Af[2][2][4], Bf[2][4][4];

    g2_load_stage(sb, 0, 0, W2h, base, m0, n, n0, tid);
    g2_load_stage(sb, 1, 1, W2h, base, m0, n, n0, tid);
    g2_load_stage(sb, 2, 2, W2h, base, m0, n, n0, tid);
    CP_WAIT2();
    __syncthreads();
    ldmx4(Af[0][0], aAddr);
    ldmx4(Af[0][1], aAddr + 16 * 144);
    #pragma unroll
    for (int p = 0; p < 4; p++)
        ldmx4t(Bf[0][p], bAddr + p * 32);

    const int NC = FF / 64;   // 64 chunks
    for (int c = 0; c < NC; c++) {
        const int s = c % 3;
        const uint32_t aS = aAddr + s * G2_A_STG;
        const uint32_t bS = bAddr + s * G2_B_STG;

        #pragma unroll
        for (int ks = 0; ks < 4; ks++) {
            const int cur = ks & 1;
            if (ks < 3) {
                const int nxt = cur ^ 1;
                const uint32_t ao = aS + (ks + 1) * 32;
                const uint32_t bo = bS + (ks + 1) * 4352;
                ldmx4(Af[nxt][0], ao);
                ldmx4(Af[nxt][1], ao + 16 * 144);
                #pragma unroll
                for (int p = 0; p < 4; p++)
                    ldmx4t(Bf[nxt][p], bo + p * 32);
            }
            #pragma unroll
            for (int nt = 0; nt < 8; nt++) {
                const uint32_t* b = &Bf[cur][nt >> 1][(nt & 1) * 2];
                #pragma unroll
                for (int mt = 0; mt < 2; mt++)
                    mma16(cacc[mt][nt], Af[cur][mt], b);
            }
        }

        if (c + 1 < NC) {
            if (c + 2 < NC) { CP_WAIT1(); } else { CP_WAIT0(); }
            __syncthreads();
            const int s1 = (c + 1) % 3;
            const uint32_t aN = aAddr + s1 * G2_A_STG;
            const uint32_t bN = bAddr + s1 * G2_B_STG;
            ldmx4(Af[0][0], aN);
            ldmx4(Af[0][1], aN + 16 * 144);
            #pragma unroll
            for (int p = 0; p < 4; p++)
                ldmx4t(Bf[0][p], bN + p * 32);
            if (c + 3 < NC)
                g2_load_stage(sb, s, c + 3, W2h, base, m0, n, n0, tid);
        }
    }

    // epilogue: weighted scatter-add into out
    #pragma unroll
    for (int mt = 0; mt < 2; mt++) {
        #pragma unroll
        for (int half_ = 0; half_ < 2; half_++) {
            const int r = m0 + wm * 32 + mt * 16 + g + half_ * 8;
            if (r >= n) continue;
            const int tk = g_tok[e][r];
            const float w = g_wrow[e][r];
            float* op = out + (size_t)tk * HD + n0 + wn * 64 + 2 * tig;
            #pragma unroll
            for (int nt = 0; nt < 8; nt++) {
                REDADD(op + nt * 8,     w * cacc[mt][nt][half_ * 2 + 0]);
                REDADD(op + nt * 8 + 1, w * cacc[mt][nt][half_ * 2 + 1]);
            }
        }
    }
}

// ---------------- launcher: half-split overlap, fork/join (graph-capture safe) ----------------
extern "C" void kernel_launch(void* const* d_in, const int* in_sizes, int n_in,
                              void* d_out, int out_size) {
    const float* x  = (const float*)d_in[0];
    const float* Wg = (const float*)d_in[1];
    const float* bg = (const float*)d_in[2];
    const float* W1 = (const float*)d_in[3];
    const float* W3 = (const float*)d_in[4];
    const float* W2 = (const float*)d_in[5];
    float* out = (float*)d_out;

    cudaFuncSetAttribute(gemm1_mma, cudaFuncAttributeMaxDynamicSharedMemorySize, G1_SMEM);
    cudaFuncSetAttribute(gemm2_mma, cudaFuncAttributeMaxDynamicSharedMemorySize, G2_SMEM);

    cudaStream_t sW;
    cudaStreamCreateWithFlags(&sW, cudaStreamNonBlocking);
    cudaEvent_t evStart, evW13, ev1lo, ev2lo;
    cudaEventCreateWithFlags(&evStart, cudaEventDisableTiming);
    cudaEventCreateWithFlags(&evW13,  cudaEventDisableTiming);
    cudaEventCreateWithFlags(&ev1lo,  cudaEventDisableTiming);
    cudaEventCreateWithFlags(&ev2lo,  cudaEventDisableTiming);

    // fork: weight converts on side stream, routing on main
    zero_counts_kernel<<<1, 32>>>();
    cudaEventRecord(evStart, 0);
    cudaStreamWaitEvent(sW, evStart, 0);
    cvt_w13_kernel<<<4096, 256, 0, sW>>>((const float4*)W1, (const float4*)W3);
    cudaEventRecord(evW13, sW);
    cvt_w2_kernel<<<4096, 256, 0, sW>>>((const float4*)W2);   // ordered before gemm2(lo) on sW

    routing_kernel<<<TOK, 256>>>(x, Wg, bg, out);
    cudaStreamWaitEvent(0, evW13, 0);                         // main needs W1/W3 before gemm1

    // half-split pipeline: gemm2(lo) overlaps gemm1(hi)
    gemm1_mma<<<dim3(FF / 64, TOK / 128, 4), 256, G1_SMEM>>>(0);
    cudaEventRecord(ev1lo, 0);
    gemm1_mma<<<dim3(FF / 64, TOK / 128, 4), 256, G1_SMEM>>>(4);
    cudaStreamWaitEvent(sW, ev1lo, 0);
    gemm2_mma<<<dim3(HD / 128, TOK / 128, 4), 256, G2_SMEM, sW>>>(out, 0);
    cudaEventRecord(ev2lo, sW);
    gemm2_mma<<<dim3(HD / 128, TOK / 128, 4), 256, G2_SMEM>>>(out, 4);  // main, after gemm1(hi)
    cudaStreamWaitEvent(0, ev2lo, 0);                         // join side stream
}